// round 2
// baseline (speedup 1.0000x reference)
#include <cuda_runtime.h>
#include <math.h>

#define C       128
#define NUSER   100000
#define NITEM   200000
#define NEDGE   1500000
#define GROUP   64
#define GTHREADS 512

// ---------------- scratch (device globals: allocation-free) ----------------
__device__ float g_m_user[(size_t)NUSER * C];
__device__ float g_m_item[(size_t)NITEM * C];
__device__ int   g_cnt_user[NUSER];
__device__ int   g_cnt_item[NITEM];
__device__ int   g_ind_user[NUSER + 1];
__device__ int   g_ind_item[NITEM + 1];
__device__ int   g_cur_user[NUSER];
__device__ int   g_cur_item[NITEM];
__device__ int   g_csr_user[NEDGE];   // sources (items) for user-destination edges
__device__ int   g_csr_item[NEDGE];   // sources (users) for item-destination edges
__device__ int   g_bs_user[1024];
__device__ int   g_bs_item[1024];

// ---------------- small helpers ----------------
__device__ __forceinline__ void fma4(float4& acc, float a, const float4& v) {
    acc.x = fmaf(a, v.x, acc.x);
    acc.y = fmaf(a, v.y, acc.y);
    acc.z = fmaf(a, v.z, acc.z);
    acc.w = fmaf(a, v.w, acc.w);
}

// 4 nodes per warp, 4 contiguous outputs per lane, K=128 sweep over smem.
__device__ __forceinline__ void gemm_tile(const float* __restrict__ Wt,
                                          const float* __restrict__ rows,
                                          int warp, int lane, float4 acc[4]) {
    const float* r0 = rows + (size_t)(warp * 4 + 0) * C;
    const float* r1 = rows + (size_t)(warp * 4 + 1) * C;
    const float* r2 = rows + (size_t)(warp * 4 + 2) * C;
    const float* r3 = rows + (size_t)(warp * 4 + 3) * C;
#pragma unroll 4
    for (int k = 0; k < C; k += 4) {
        float4 w0 = ((const float4*)(Wt + (size_t)(k + 0) * C))[lane];
        float4 w1 = ((const float4*)(Wt + (size_t)(k + 1) * C))[lane];
        float4 w2 = ((const float4*)(Wt + (size_t)(k + 2) * C))[lane];
        float4 w3 = ((const float4*)(Wt + (size_t)(k + 3) * C))[lane];
        float4 a0 = *(const float4*)(r0 + k);
        float4 a1 = *(const float4*)(r1 + k);
        float4 a2 = *(const float4*)(r2 + k);
        float4 a3 = *(const float4*)(r3 + k);
        fma4(acc[0], a0.x, w0); fma4(acc[0], a0.y, w1); fma4(acc[0], a0.z, w2); fma4(acc[0], a0.w, w3);
        fma4(acc[1], a1.x, w0); fma4(acc[1], a1.y, w1); fma4(acc[1], a1.z, w2); fma4(acc[1], a1.w, w3);
        fma4(acc[2], a2.x, w0); fma4(acc[2], a2.y, w1); fma4(acc[2], a2.z, w2); fma4(acc[2], a2.w, w3);
        fma4(acc[3], a3.x, w0); fma4(acc[3], a3.y, w1); fma4(acc[3], a3.z, w2); fma4(acc[3], a3.w, w3);
    }
}

// ---------------- CSR build ----------------
__global__ void k_zero2(int* a, int na, int* b, int nb) {
    int stride = gridDim.x * blockDim.x;
    for (int i = blockIdx.x * blockDim.x + threadIdx.x; i < na; i += stride) a[i] = 0;
    for (int i = blockIdx.x * blockDim.x + threadIdx.x; i < nb; i += stride) b[i] = 0;
}

__global__ void k_hist(const int* __restrict__ dst, int ne, int* __restrict__ cnt) {
    int i = blockIdx.x * blockDim.x + threadIdx.x;
    if (i < ne) atomicAdd(&cnt[dst[i]], 1);
}

__global__ void k_scan_block(const int* __restrict__ cnt, int n,
                             int* __restrict__ indptr, int* __restrict__ bsums) {
    __shared__ int sm[1024];
    int i = blockIdx.x * 1024 + threadIdx.x;
    int v = (i < n) ? cnt[i] : 0;
    sm[threadIdx.x] = v;
    __syncthreads();
#pragma unroll
    for (int off = 1; off < 1024; off <<= 1) {
        int t = (threadIdx.x >= off) ? sm[threadIdx.x - off] : 0;
        __syncthreads();
        sm[threadIdx.x] += t;
        __syncthreads();
    }
    if (i < n) indptr[i + 1] = sm[threadIdx.x];
    if (threadIdx.x == 1023) bsums[blockIdx.x] = sm[1023];
}

__global__ void k_scan_bsums(int* __restrict__ bs, int nb) {
    __shared__ int sm[1024];
    int v = (threadIdx.x < nb) ? bs[threadIdx.x] : 0;
    sm[threadIdx.x] = v;
    __syncthreads();
#pragma unroll
    for (int off = 1; off < 1024; off <<= 1) {
        int t = (threadIdx.x >= off) ? sm[threadIdx.x - off] : 0;
        __syncthreads();
        sm[threadIdx.x] += t;
        __syncthreads();
    }
    if (threadIdx.x < nb) bs[threadIdx.x] = sm[threadIdx.x] - v;  // exclusive
}

__global__ void k_scan_final(const int* __restrict__ cnt, int n,
                             int* __restrict__ indptr, const int* __restrict__ bsex,
                             int* __restrict__ cursor) {
    int i = blockIdx.x * blockDim.x + threadIdx.x;
    if (i < n) {
        int incl = indptr[i + 1] + bsex[i >> 10];
        indptr[i + 1] = incl;
        cursor[i] = incl - cnt[i];
    }
    if (i == 0) indptr[0] = 0;
}

__global__ void k_scatter(const int* __restrict__ src, const int* __restrict__ dst, int ne,
                          int* __restrict__ cursor, int* __restrict__ csr) {
    int i = blockIdx.x * blockDim.x + threadIdx.x;
    if (i < ne) {
        int p = atomicAdd(&cursor[dst[i]], 1);
        csr[p] = src[i];
    }
}

// ---------------- mean aggregation (1 warp per destination node) ----------------
__global__ void k_agg(const float* __restrict__ xs, const int* __restrict__ indptr,
                      const int* __restrict__ csr, float* __restrict__ m, int n) {
    int node = (blockIdx.x * blockDim.x + threadIdx.x) >> 5;
    int lane = threadIdx.x & 31;
    if (node >= n) return;
    int beg = indptr[node], end = indptr[node + 1];
    float4 acc = make_float4(0.f, 0.f, 0.f, 0.f);
    int j = beg;
    for (; j + 2 <= end; j += 2) {
        int s0 = csr[j], s1 = csr[j + 1];
        float4 v0 = ((const float4*)(xs + (size_t)s0 * C))[lane];
        float4 v1 = ((const float4*)(xs + (size_t)s1 * C))[lane];
        acc.x += v0.x; acc.y += v0.y; acc.z += v0.z; acc.w += v0.w;
        acc.x += v1.x; acc.y += v1.y; acc.z += v1.z; acc.w += v1.w;
    }
    if (j < end) {
        int s = csr[j];
        float4 v = ((const float4*)(xs + (size_t)s * C))[lane];
        acc.x += v.x; acc.y += v.y; acc.z += v.z; acc.w += v.w;
    }
    int deg = end - beg;
    float inv = 1.0f / (float)(deg > 0 ? deg : 1);
    float4 r = make_float4(acc.x * inv, acc.y * inv, acc.z * inv, acc.w * inv);
    ((float4*)(m + (size_t)node * C))[lane] = r;
}

// ---------------- temporal encoder: out = x + posenc(rel) @ W^T + b ----------------
// smem: Wt (64KB) + pe rows (32KB) + rel (256B)
__global__ void k_temporal(const float* __restrict__ x, const int* __restrict__ seed,
                           const int* __restrict__ tn, const int* __restrict__ bn,
                           const float* __restrict__ W, const float* __restrict__ bias,
                           float* __restrict__ out, int n) {
    extern __shared__ float sm[];
    float* Wt   = sm;                       // [128][128] transposed: Wt[k][c]
    float* rows = sm + 16384;               // [GROUP][128] positional encodings
    float* rel  = rows + GROUP * C;         // [GROUP]

    for (int idx = threadIdx.x; idx < 16384; idx += blockDim.x) {
        int k = idx >> 7, c = idx & 127;
        Wt[idx] = W[c * C + k];
    }
    int warp = threadIdx.x >> 5, lane = threadIdx.x & 31;
    float4 b4 = ((const float4*)bias)[lane];

    for (int base = blockIdx.x * GROUP; base < n; base += gridDim.x * GROUP) {
        __syncthreads();  // covers Wt on first iter, rows reuse afterwards
        if (threadIdx.x < GROUP) {
            int node = base + threadIdx.x;
            rel[threadIdx.x] = (node < n)
                ? (float)(seed[bn[node]] - tn[node]) * (1.0f / 86400.0f) : 0.0f;
        }
        __syncthreads();
        // pe[2j] = sin(rel*div_j), pe[2j+1] = cos(rel*div_j), div_j = 10000^{-2j/128}
        for (int idx = threadIdx.x; idx < GROUP * 64; idx += blockDim.x) {
            int ni = idx >> 6, j = idx & 63;
            float div = exp2f(-0.20762050593046f * (float)j);
            float ang = rel[ni] * div;
            float s, cc;
            sincosf(ang, &s, &cc);
            rows[ni * C + 2 * j]     = s;
            rows[ni * C + 2 * j + 1] = cc;
        }
        __syncthreads();

        float4 acc[4];
#pragma unroll
        for (int i = 0; i < 4; i++) acc[i] = make_float4(0.f, 0.f, 0.f, 0.f);
        gemm_tile(Wt, rows, warp, lane, acc);

#pragma unroll
        for (int i = 0; i < 4; i++) {
            int node = base + warp * 4 + i;
            if (node < n) {
                float4 xv = ((const float4*)(x + (size_t)node * C))[lane];
                float4 o;
                o.x = xv.x + acc[i].x + b4.x;
                o.y = xv.y + acc[i].y + b4.y;
                o.z = xv.z + acc[i].z + b4.z;
                o.w = xv.w + acc[i].w + b4.w;
                ((float4*)(out + (size_t)node * C))[lane] = o;
            }
        }
    }
}

// ---------------- SAGE layer: x = relu(LN(m@Wl^T + b + x@Wr^T)) (in-place) --------
// smem: Wlt (64KB) + Wrt (64KB) + m rows (32KB) + x rows (32KB) = 192KB
__global__ void k_sage(const float* __restrict__ m, float* x,
                       const float* __restrict__ Wl, const float* __restrict__ bias,
                       const float* __restrict__ Wr,
                       const float* __restrict__ gam, const float* __restrict__ bet, int n) {
    extern __shared__ float sm[];
    float* Wlt = sm;
    float* Wrt = sm + 16384;
    float* rm  = sm + 32768;
    float* rx  = rm + GROUP * C;

    for (int idx = threadIdx.x; idx < 16384; idx += blockDim.x) {
        int k = idx >> 7, c = idx & 127;
        Wlt[idx] = Wl[c * C + k];
        Wrt[idx] = Wr[c * C + k];
    }
    int warp = threadIdx.x >> 5, lane = threadIdx.x & 31;
    float4 b4 = ((const float4*)bias)[lane];
    float4 g4 = ((const float4*)gam)[lane];
    float4 e4 = ((const float4*)bet)[lane];

    for (int base = blockIdx.x * GROUP; base < n; base += gridDim.x * GROUP) {
        __syncthreads();
        int cnt4 = (n - base < GROUP ? n - base : GROUP) * (C / 4);
        for (int idx = threadIdx.x; idx < cnt4; idx += blockDim.x) {
            ((float4*)rm)[idx] = ((const float4*)(m + (size_t)base * C))[idx];
            ((float4*)rx)[idx] = ((const float4*)(x + (size_t)base * C))[idx];
        }
        __syncthreads();

        float4 acc[4];
#pragma unroll
        for (int i = 0; i < 4; i++) acc[i] = make_float4(0.f, 0.f, 0.f, 0.f);
        gemm_tile(Wlt, rm, warp, lane, acc);
        gemm_tile(Wrt, rx, warp, lane, acc);

#pragma unroll
        for (int i = 0; i < 4; i++) {
            int node = base + warp * 4 + i;
            if (node < n) {
                float4 v = acc[i];
                v.x += b4.x; v.y += b4.y; v.z += b4.z; v.w += b4.w;
                float s1 = v.x + v.y + v.z + v.w;
                float s2 = v.x * v.x + v.y * v.y + v.z * v.z + v.w * v.w;
#pragma unroll
                for (int off = 16; off > 0; off >>= 1) {
                    s1 += __shfl_xor_sync(0xFFFFFFFFu, s1, off);
                    s2 += __shfl_xor_sync(0xFFFFFFFFu, s2, off);
                }
                float mean = s1 * (1.0f / 128.0f);
                float var  = s2 * (1.0f / 128.0f) - mean * mean;
                float rstd = rsqrtf(var + 1e-5f);
                float4 o;
                o.x = fmaxf(0.f, (v.x - mean) * rstd * g4.x + e4.x);
                o.y = fmaxf(0.f, (v.y - mean) * rstd * g4.y + e4.y);
                o.z = fmaxf(0.f, (v.z - mean) * rstd * g4.z + e4.z);
                o.w = fmaxf(0.f, (v.w - mean) * rstd * g4.w + e4.w);
                ((float4*)(x + (size_t)node * C))[lane] = o;
            }
        }
    }
}

// ---------------- launch ----------------
#define TEMP_SMEM ((16384 + GROUP * C + GROUP) * 4)
#define SAGE_SMEM ((32768 + 2 * GROUP * C) * 4)

extern "C" void kernel_launch(void* const* d_in, const int* in_sizes, int n_in,
                              void* d_out, int out_size) {
    const float* x_user = (const float*)d_in[0];
    const float* x_item = (const float*)d_in[1];
    const int*   seed   = (const int*)d_in[2];
    const int*   t_user = (const int*)d_in[3];
    const int*   t_item = (const int*)d_in[4];
    const int*   b_user = (const int*)d_in[5];
    const int*   b_item = (const int*)d_in[6];
    const int*   src_ui = (const int*)d_in[7];
    const int*   dst_ui = (const int*)d_in[8];
    const int*   src_iu = (const int*)d_in[9];
    const int*   dst_iu = (const int*)d_in[10];
    const float* teWu   = (const float*)d_in[11];
    const float* tebu   = (const float*)d_in[12];
    const float* teWi   = (const float*)d_in[13];
    const float* tebi   = (const float*)d_in[14];
    const float* Wl_ui  = (const float*)d_in[15];
    const float* bl_ui  = (const float*)d_in[16];
    const float* Wr_ui  = (const float*)d_in[17];
    const float* Wl_iu  = (const float*)d_in[18];
    const float* bl_iu  = (const float*)d_in[19];
    const float* Wr_iu  = (const float*)d_in[20];
    const float* g_u    = (const float*)d_in[21];
    const float* be_u   = (const float*)d_in[22];
    const float* g_i    = (const float*)d_in[23];
    const float* be_i   = (const float*)d_in[24];

    float* xu = (float*)d_out;                 // user activations live in d_out
    float* xi = xu + (size_t)NUSER * C;        // item activations follow

    cudaFuncSetAttribute(k_temporal, cudaFuncAttributeMaxDynamicSharedMemorySize, TEMP_SMEM);
    cudaFuncSetAttribute(k_sage,     cudaFuncAttributeMaxDynamicSharedMemorySize, SAGE_SMEM);

    float *m_user, *m_item;
    int *cnt_u, *cnt_i, *ind_u, *ind_i, *cur_u, *cur_i, *csr_u, *csr_i, *bs_u, *bs_i;
    cudaGetSymbolAddress((void**)&m_user, g_m_user);
    cudaGetSymbolAddress((void**)&m_item, g_m_item);
    cudaGetSymbolAddress((void**)&cnt_u, g_cnt_user);
    cudaGetSymbolAddress((void**)&cnt_i, g_cnt_item);
    cudaGetSymbolAddress((void**)&ind_u, g_ind_user);
    cudaGetSymbolAddress((void**)&ind_i, g_ind_item);
    cudaGetSymbolAddress((void**)&cur_u, g_cur_user);
    cudaGetSymbolAddress((void**)&cur_i, g_cur_item);
    cudaGetSymbolAddress((void**)&csr_u, g_csr_user);
    cudaGetSymbolAddress((void**)&csr_i, g_csr_item);
    cudaGetSymbolAddress((void**)&bs_u, g_bs_user);
    cudaGetSymbolAddress((void**)&bs_i, g_bs_item);

    const int EB = (NEDGE + 255) / 256;
    const int IB_U = (NUSER + 1023) / 1024;   // 98
    const int IB_I = (NITEM + 1023) / 1024;   // 196

    // ---- CSR build (must be rebuilt every call: counters are consumed) ----
    k_zero2<<<512, 256>>>(cnt_i, NITEM, cnt_u, NUSER);
    k_hist<<<EB, 256>>>(dst_ui, NEDGE, cnt_i);
    k_hist<<<EB, 256>>>(dst_iu, NEDGE, cnt_u);
    k_scan_block<<<IB_I, 1024>>>(cnt_i, NITEM, ind_i, bs_i);
    k_scan_block<<<IB_U, 1024>>>(cnt_u, NUSER, ind_u, bs_u);
    k_scan_bsums<<<1, 1024>>>(bs_i, IB_I);
    k_scan_bsums<<<1, 1024>>>(bs_u, IB_U);
    k_scan_final<<<(NITEM + 255) / 256, 256>>>(cnt_i, NITEM, ind_i, bs_i, cur_i);
    k_scan_final<<<(NUSER + 255) / 256, 256>>>(cnt_u, NUSER, ind_u, bs_u, cur_u);
    k_scatter<<<EB, 256>>>(src_ui, dst_ui, NEDGE, cur_i, csr_i);
    k_scatter<<<EB, 256>>>(src_iu, dst_iu, NEDGE, cur_u, csr_u);

    // ---- temporal encoder (writes activations into d_out) ----
    k_temporal<<<296, GTHREADS, TEMP_SMEM>>>(x_user, seed, t_user, b_user, teWu, tebu, xu, NUSER);
    k_temporal<<<296, GTHREADS, TEMP_SMEM>>>(x_item, seed, t_item, b_item, teWi, tebi, xi, NITEM);

    // ---- 2 SAGE layers ----
    for (int l = 0; l < 2; l++) {
        size_t wo = (size_t)l * C * C;
        size_t vo = (size_t)l * C;
        k_agg<<<(NITEM * 32 + 255) / 256, 256>>>(xu, ind_i, csr_i, m_item, NITEM);
        k_agg<<<(NUSER * 32 + 255) / 256, 256>>>(xi, ind_u, csr_u, m_user, NUSER);
        k_sage<<<148, GTHREADS, SAGE_SMEM>>>(m_item, xi, Wl_ui + wo, bl_ui + vo, Wr_ui + wo,
                                             g_i + vo, be_i + vo, NITEM);
        k_sage<<<148, GTHREADS, SAGE_SMEM>>>(m_user, xu, Wl_iu + wo, bl_iu + vo, Wr_iu + wo,
                                             g_u + vo, be_u + vo, NUSER);
    }
}

// round 5
// speedup vs baseline: 1.4748x; 1.4748x over previous
#include <cuda_runtime.h>
#include <cuda_bf16.h>
#include <math.h>
#include <stdint.h>

#define C       128
#define NUSER   100000
#define NITEM   200000
#define NEDGE   1500000
#define TM      128
#define TPB     256
#define SA      136            // smem row stride in bf16 elems (pad vs 128)
#define TILE_B  (128 * SA * 2) // bytes per bf16 tile: 34816

// ---------------- scratch (device globals: allocation-free) ----------------
__device__ float g_m_user[(size_t)NUSER * C];
__device__ float g_m_item[(size_t)NITEM * C];
__device__ int   g_cnt_user[NUSER];
__device__ int   g_cnt_item[NITEM];
__device__ int   g_ind_user[NUSER + 1];
__device__ int   g_ind_item[NITEM + 1];
__device__ int   g_cur_user[NUSER];
__device__ int   g_cur_item[NITEM];
__device__ int   g_csr_user[NEDGE];
__device__ int   g_csr_item[NEDGE];
__device__ int   g_bs_user[1024];
__device__ int   g_bs_item[1024];

// ---------------- warp MMA helpers ----------------
__device__ __forceinline__ uint32_t smem_u32(const void* p) {
    uint32_t a;
    asm("{ .reg .u64 t; cvta.to.shared.u64 t, %1; cvt.u32.u64 %0, t; }" : "=r"(a) : "l"(p));
    return a;
}
__device__ __forceinline__ void ldmx4(uint32_t* r, uint32_t addr) {
    asm volatile("ldmatrix.sync.aligned.m8n8.x4.shared.b16 {%0,%1,%2,%3}, [%4];"
                 : "=r"(r[0]), "=r"(r[1]), "=r"(r[2]), "=r"(r[3]) : "r"(addr));
}
__device__ __forceinline__ void ldmx2(uint32_t* r, uint32_t addr) {
    asm volatile("ldmatrix.sync.aligned.m8n8.x2.shared.b16 {%0,%1}, [%2];"
                 : "=r"(r[0]), "=r"(r[1]) : "r"(addr));
}
__device__ __forceinline__ void mma16816(float* c, const uint32_t* a, const uint32_t* b) {
    asm volatile("mma.sync.aligned.m16n8k16.row.col.f32.bf16.bf16.f32 "
                 "{%0,%1,%2,%3},{%4,%5,%6,%7},{%8,%9},{%0,%1,%2,%3};"
                 : "+f"(c[0]), "+f"(c[1]), "+f"(c[2]), "+f"(c[3])
                 : "r"(a[0]), "r"(a[1]), "r"(a[2]), "r"(a[3]), "r"(b[0]), "r"(b[1]));
}

// One warp: rows [w*16, w*16+16) x all 128 cols. 3-term split accumulate.
// A tiles: [128][SA] bf16 (hi/lo), W tiles: [128 n][SA k] bf16 (hi/lo).
__device__ __forceinline__ void mma_gemm(uint32_t aH, uint32_t aL, uint32_t bH, uint32_t bL,
                                         int w, int l, float acc[16][4]) {
    int arow = w * 16 + (l & 7) + ((l >> 3) & 1) * 8;
    int acol = ((l >> 4) & 1) * 8;
    uint32_t aoff = (uint32_t)(arow * SA + acol) * 2;
    int l8 = l & 15;
    uint32_t bbase = (uint32_t)((l8 & 7) * SA + ((l8 >> 3) & 1) * 8) * 2;
#pragma unroll
    for (int k = 0; k < 8; k++) {
        uint32_t ah[4], al[4];
        ldmx4(ah, aH + aoff + k * 32);
        ldmx4(al, aL + aoff + k * 32);
#pragma unroll
        for (int nt = 0; nt < 16; nt++) {
            uint32_t boff = bbase + (uint32_t)(nt * 8 * SA) * 2 + k * 32;
            uint32_t bh[2], bl[2];
            ldmx2(bh, bH + boff);
            ldmx2(bl, bL + boff);
            mma16816(acc[nt], ah, bh);
            mma16816(acc[nt], ah, bl);
            mma16816(acc[nt], al, bh);
        }
    }
}

// fp32 -> (hi, lo) bf16 split store into padded tile layout
__device__ __forceinline__ void split_store4(char* hi, char* lo, int row, int col, float4 v) {
    uint32_t off = (uint32_t)(row * SA + col) * 2;
    __nv_bfloat162 h01 = __floats2bfloat162_rn(v.x, v.y);
    __nv_bfloat162 h23 = __floats2bfloat162_rn(v.z, v.w);
    float lx = v.x - __low2float(h01);
    float ly = v.y - __high2float(h01);
    float lz = v.z - __low2float(h23);
    float lw = v.w - __high2float(h23);
    __nv_bfloat162 l01 = __floats2bfloat162_rn(lx, ly);
    __nv_bfloat162 l23 = __floats2bfloat162_rn(lz, lw);
    uint2 hp, lp;
    hp.x = *(uint32_t*)&h01; hp.y = *(uint32_t*)&h23;
    lp.x = *(uint32_t*)&l01; lp.y = *(uint32_t*)&l23;
    *(uint2*)(hi + off) = hp;
    *(uint2*)(lo + off) = lp;
}

__device__ __forceinline__ void load_weight_tile(const float* __restrict__ W,
                                                 char* hi, char* lo, int tid) {
#pragma unroll 4
    for (int idx = tid; idx < 4096; idx += TPB) {
        int row = idx >> 5, col = (idx & 31) << 2;
        float4 v = *(const float4*)(W + row * C + col);
        split_store4(hi, lo, row, col, v);
    }
}

__device__ __forceinline__ void load_act_tile(const float* __restrict__ X, size_t base, int rv,
                                              char* hi, char* lo, int tid) {
#pragma unroll 4
    for (int idx = tid; idx < 4096; idx += TPB) {
        int row = idx >> 5, col = (idx & 31) << 2;
        float4 v = (row < rv) ? *(const float4*)(X + (base + row) * (size_t)C + col)
                              : make_float4(0.f, 0.f, 0.f, 0.f);
        split_store4(hi, lo, row, col, v);
    }
}

// ---------------- CSR build ----------------
__global__ void k_zero2(int* a, int na, int* b, int nb) {
    int stride = gridDim.x * blockDim.x;
    for (int i = blockIdx.x * blockDim.x + threadIdx.x; i < na; i += stride) a[i] = 0;
    for (int i = blockIdx.x * blockDim.x + threadIdx.x; i < nb; i += stride) b[i] = 0;
}
__global__ void k_hist(const int* __restrict__ dst, int ne, int* __restrict__ cnt) {
    int i = blockIdx.x * blockDim.x + threadIdx.x;
    if (i < ne) atomicAdd(&cnt[dst[i]], 1);
}
__global__ void k_scan_block(const int* __restrict__ cnt, int n,
                             int* __restrict__ indptr, int* __restrict__ bsums) {
    __shared__ int sm[1024];
    int i = blockIdx.x * 1024 + threadIdx.x;
    int v = (i < n) ? cnt[i] : 0;
    sm[threadIdx.x] = v;
    __syncthreads();
#pragma unroll
    for (int off = 1; off < 1024; off <<= 1) {
        int t = (threadIdx.x >= off) ? sm[threadIdx.x - off] : 0;
        __syncthreads();
        sm[threadIdx.x] += t;
        __syncthreads();
    }
    if (i < n) indptr[i + 1] = sm[threadIdx.x];
    if (threadIdx.x == 1023) bsums[blockIdx.x] = sm[1023];
}
__global__ void k_scan_bsums(int* __restrict__ bs, int nb) {
    __shared__ int sm[1024];
    int v = (threadIdx.x < nb) ? bs[threadIdx.x] : 0;
    sm[threadIdx.x] = v;
    __syncthreads();
#pragma unroll
    for (int off = 1; off < 1024; off <<= 1) {
        int t = (threadIdx.x >= off) ? sm[threadIdx.x - off] : 0;
        __syncthreads();
        sm[threadIdx.x] += t;
        __syncthreads();
    }
    if (threadIdx.x < nb) bs[threadIdx.x] = sm[threadIdx.x] - v;
}
__global__ void k_scan_final(const int* __restrict__ cnt, int n,
                             int* __restrict__ indptr, const int* __restrict__ bsex,
                             int* __restrict__ cursor) {
    int i = blockIdx.x * blockDim.x + threadIdx.x;
    if (i < n) {
        int incl = indptr[i + 1] + bsex[i >> 10];
        indptr[i + 1] = incl;
        cursor[i] = incl - cnt[i];
    }
    if (i == 0) indptr[0] = 0;
}
__global__ void k_scatter(const int* __restrict__ src, const int* __restrict__ dst, int ne,
                          int* __restrict__ cursor, int* __restrict__ csr) {
    int i = blockIdx.x * blockDim.x + threadIdx.x;
    if (i < ne) {
        int p = atomicAdd(&cursor[dst[i]], 1);
        csr[p] = src[i];
    }
}

// ---------------- mean aggregation (1 warp per destination node) ----------------
__global__ void k_agg(const float* __restrict__ xs, const int* __restrict__ indptr,
                      const int* __restrict__ csr, float* __restrict__ m, int n) {
    int node = (blockIdx.x * blockDim.x + threadIdx.x) >> 5;
    int lane = threadIdx.x & 31;
    if (node >= n) return;
    int beg = indptr[node], end = indptr[node + 1];
    float4 acc = make_float4(0.f, 0.f, 0.f, 0.f);
    int j = beg;
    for (; j + 2 <= end; j += 2) {
        int s0 = csr[j], s1 = csr[j + 1];
        float4 v0 = ((const float4*)(xs + (size_t)s0 * C))[lane];
        float4 v1 = ((const float4*)(xs + (size_t)s1 * C))[lane];
        acc.x += v0.x; acc.y += v0.y; acc.z += v0.z; acc.w += v0.w;
        acc.x += v1.x; acc.y += v1.y; acc.z += v1.z; acc.w += v1.w;
    }
    if (j < end) {
        int s = csr[j];
        float4 v = ((const float4*)(xs + (size_t)s * C))[lane];
        acc.x += v.x; acc.y += v.y; acc.z += v.z; acc.w += v.w;
    }
    int deg = end - beg;
    float inv = 1.0f / (float)(deg > 0 ? deg : 1);
    ((float4*)(m + (size_t)node * C))[lane] =
        make_float4(acc.x * inv, acc.y * inv, acc.z * inv, acc.w * inv);
}

// ---------------- temporal encoder (mma): out = x + posenc(rel) @ W^T + b ----------
#define T_WH 0
#define T_WL (TILE_B)
#define T_AH (2 * TILE_B)
#define T_AL (3 * TILE_B)
#define T_BIAS (4 * TILE_B)
#define T_REL (4 * TILE_B + 512)
#define TEMP_SMEM (4 * TILE_B + 1024)

__global__ void __launch_bounds__(TPB) k_temporal_mma(
    const float* __restrict__ x, const int* __restrict__ seed,
    const int* __restrict__ tn, const int* __restrict__ bn,
    const float* __restrict__ W, const float* __restrict__ bias,
    float* __restrict__ out, int n)
{
    extern __shared__ char sm[];
    char* AH = sm + T_AH; char* ALo = sm + T_AL;
    float* sbias = (float*)(sm + T_BIAS);
    float* srel  = (float*)(sm + T_REL);
    uint32_t sb = smem_u32(sm);
    int tid = threadIdx.x, w = tid >> 5, l = tid & 31;

    load_weight_tile(W, sm + T_WH, sm + T_WL, tid);
    if (tid < 128) sbias[tid] = bias[tid];

    int ntiles = (n + TM - 1) / TM;
    for (int t = blockIdx.x; t < ntiles; t += gridDim.x) {
        size_t base = (size_t)t * TM;
        int rv = min(TM, n - (int)base);
        __syncthreads();
        if (tid < 128) {
            int node = (int)base + tid;
            srel[tid] = (tid < rv) ? (float)(seed[bn[node]] - tn[node]) * (1.0f / 86400.0f) : 0.0f;
        }
        __syncthreads();
#pragma unroll 4
        for (int idx = tid; idx < 128 * 64; idx += TPB) {
            int r = idx >> 6, j = idx & 63;
            float div = exp2f(-0.20762050593046f * (float)j);
            float ang = srel[r] * div;
            float s, c;
            sincosf(ang, &s, &c);
            uint32_t off = (uint32_t)(r * SA + 2 * j) * 2;
            __nv_bfloat162 h = __floats2bfloat162_rn(s, c);
            float ls = s - __low2float(h), lc = c - __high2float(h);
            __nv_bfloat162 lw = __floats2bfloat162_rn(ls, lc);
            *(uint32_t*)(AH + off)  = *(uint32_t*)&h;
            *(uint32_t*)(ALo + off) = *(uint32_t*)&lw;
        }
        __syncthreads();

        float acc[16][4];
#pragma unroll
        for (int i = 0; i < 16; i++)
            acc[i][0] = acc[i][1] = acc[i][2] = acc[i][3] = 0.f;
        mma_gemm(sb + T_AH, sb + T_AL, sb + T_WH, sb + T_WL, w, l, acc);

        int qrow = l >> 2, qcol = (l & 3) * 2;
        int r0 = w * 16 + qrow, r1 = r0 + 8;
#pragma unroll
        for (int nt = 0; nt < 16; nt++) {
            int c0 = nt * 8 + qcol;
            if (r0 < rv) {
                const float* xr = x + (base + r0) * (size_t)C + c0;
                float2 xv = *(const float2*)xr;
                float2 o;
                o.x = acc[nt][0] + xv.x + sbias[c0];
                o.y = acc[nt][1] + xv.y + sbias[c0 + 1];
                *(float2*)(out + (base + r0) * (size_t)C + c0) = o;
            }
            if (r1 < rv) {
                const float* xr = x + (base + r1) * (size_t)C + c0;
                float2 xv = *(const float2*)xr;
                float2 o;
                o.x = acc[nt][2] + xv.x + sbias[c0];
                o.y = acc[nt][3] + xv.y + sbias[c0 + 1];
                *(float2*)(out + (base + r1) * (size_t)C + c0) = o;
            }
        }
        __syncthreads();
    }
}

// ---------------- SAGE layer (mma): x = relu(LN(m@Wl^T + b + x@Wr^T)) in-place -----
#define S_WLH 0
#define S_WLL (TILE_B)
#define S_WRH (2 * TILE_B)
#define S_WRL (3 * TILE_B)
#define S_AH  (4 * TILE_B)
#define S_AL  (5 * TILE_B)
#define S_BIAS (6 * TILE_B)
#define S_GAM  (6 * TILE_B + 512)
#define S_BET  (6 * TILE_B + 1024)
#define SAGE_SMEM (6 * TILE_B + 1536)

__global__ void __launch_bounds__(TPB) k_sage_mma(
    const float* __restrict__ m, float* __restrict__ x,
    const float* __restrict__ Wl, const float* __restrict__ bias,
    const float* __restrict__ Wr, const float* __restrict__ gam,
    const float* __restrict__ bet, int n)
{
    extern __shared__ char sm[];
    float* sbias = (float*)(sm + S_BIAS);
    float* sgam  = (float*)(sm + S_GAM);
    float* sbet  = (float*)(sm + S_BET);
    uint32_t sb = smem_u32(sm);
    int tid = threadIdx.x, w = tid >> 5, l = tid & 31;

    load_weight_tile(Wl, sm + S_WLH, sm + S_WLL, tid);
    load_weight_tile(Wr, sm + S_WRH, sm + S_WRL, tid);
    if (tid < 128) { sbias[tid] = bias[tid]; sgam[tid] = gam[tid]; sbet[tid] = bet[tid]; }

    int ntiles = (n + TM - 1) / TM;
    for (int t = blockIdx.x; t < ntiles; t += gridDim.x) {
        size_t base = (size_t)t * TM;
        int rv = min(TM, n - (int)base);

        __syncthreads();
        load_act_tile(m, base, rv, sm + S_AH, sm + S_AL, tid);
        __syncthreads();

        float acc[16][4];
#pragma unroll
        for (int i = 0; i < 16; i++)
            acc[i][0] = acc[i][1] = acc[i][2] = acc[i][3] = 0.f;
        mma_gemm(sb + S_AH, sb + S_AL, sb + S_WLH, sb + S_WLL, w, l, acc);

        __syncthreads();
        load_act_tile(x, base, rv, sm + S_AH, sm + S_AL, tid);
        __syncthreads();
        mma_gemm(sb + S_AH, sb + S_AL, sb + S_WRH, sb + S_WRL, w, l, acc);

        // bias + LayerNorm + ReLU; each row is owned by one lane-quad
        int qrow = l >> 2, qcol = (l & 3) * 2;
        int r0 = w * 16 + qrow, r1 = r0 + 8;
        float s1a = 0.f, s2a = 0.f, s1b = 0.f, s2b = 0.f;
#pragma unroll
        for (int nt = 0; nt < 16; nt++) {
            int c0 = nt * 8 + qcol;
            float v0 = acc[nt][0] + sbias[c0];
            float v1 = acc[nt][1] + sbias[c0 + 1];
            float v2 = acc[nt][2] + sbias[c0];
            float v3 = acc[nt][3] + sbias[c0 + 1];
            acc[nt][0] = v0; acc[nt][1] = v1; acc[nt][2] = v2; acc[nt][3] = v3;
            s1a += v0 + v1; s2a += v0 * v0 + v1 * v1;
            s1b += v2 + v3; s2b += v2 * v2 + v3 * v3;
        }
#pragma unroll
        for (int off = 1; off <= 2; off <<= 1) {
            s1a += __shfl_xor_sync(0xFFFFFFFFu, s1a, off);
            s2a += __shfl_xor_sync(0xFFFFFFFFu, s2a, off);
            s1b += __shfl_xor_sync(0xFFFFFFFFu, s1b, off);
            s2b += __shfl_xor_sync(0xFFFFFFFFu, s2b, off);
        }
        float mean0 = s1a * (1.0f / 128.0f);
        float var0  = s2a * (1.0f / 128.0f) - mean0 * mean0;
        float rstd0 = rsqrtf(var0 + 1e-5f);
        float mean1 = s1b * (1.0f / 128.0f);
        float var1  = s2b * (1.0f / 128.0f) - mean1 * mean1;
        float rstd1 = rsqrtf(var1 + 1e-5f);
#pragma unroll
        for (int nt = 0; nt < 16; nt++) {
            int c0 = nt * 8 + qcol;
            if (r0 < rv) {
                float2 o;
                o.x = fmaxf(0.f, (acc[nt][0] - mean0) * rstd0 * sgam[c0] + sbet[c0]);
                o.y = fmaxf(0.f, (acc[nt][1] - mean0) * rstd0 * sgam[c0 + 1] + sbet[c0 + 1]);
                *(float2*)(x + (base + r0) * (size_t)C + c0) = o;
            }
            if (r1 < rv) {
                float2 o;
                o.x = fmaxf(0.f, (acc[nt][2] - mean1) * rstd1 * sgam[c0] + sbet[c0]);
                o.y = fmaxf(0.f, (acc[nt][3] - mean1) * rstd1 * sgam[c0 + 1] + sbet[c0 + 1]);
                *(float2*)(x + (base + r1) * (size_t)C + c0) = o;
            }
        }
        __syncthreads();
    }
}

// ---------------- launch ----------------
extern "C" void kernel_launch(void* const* d_in, const int* in_sizes, int n_in,
                              void* d_out, int out_size) {
    const float* x_user = (const float*)d_in[0];
    const float* x_item = (const float*)d_in[1];
    const int*   seed   = (const int*)d_in[2];
    const int*   t_user = (const int*)d_in[3];
    const int*   t_item = (const int*)d_in[4];
    const int*   b_user = (const int*)d_in[5];
    const int*   b_item = (const int*)d_in[6];
    const int*   src_ui = (const int*)d_in[7];
    const int*   dst_ui = (const int*)d_in[8];
    const int*   src_iu = (const int*)d_in[9];
    const int*   dst_iu = (const int*)d_in[10];
    const float* teWu   = (const float*)d_in[11];
    const float* tebu   = (const float*)d_in[12];
    const float* teWi   = (const float*)d_in[13];
    const float* tebi   = (const float*)d_in[14];
    const float* Wl_ui  = (const float*)d_in[15];
    const float* bl_ui  = (const float*)d_in[16];
    const float* Wr_ui  = (const float*)d_in[17];
    const float* Wl_iu  = (const float*)d_in[18];
    const float* bl_iu  = (const float*)d_in[19];
    const float* Wr_iu  = (const float*)d_in[20];
    const float* g_u    = (const float*)d_in[21];
    const float* be_u   = (const float*)d_in[22];
    const float* g_i    = (const float*)d_in[23];
    const float* be_i   = (const float*)d_in[24];

    float* xu = (float*)d_out;
    float* xi = xu + (size_t)NUSER * C;

    cudaFuncSetAttribute(k_temporal_mma, cudaFuncAttributeMaxDynamicSharedMemorySize, TEMP_SMEM);
    cudaFuncSetAttribute(k_sage_mma,     cudaFuncAttributeMaxDynamicSharedMemorySize, SAGE_SMEM);

    float *m_user, *m_item;
    int *cnt_u, *cnt_i, *ind_u, *ind_i, *cur_u, *cur_i, *csr_u, *csr_i, *bs_u, *bs_i;
    cudaGetSymbolAddress((void**)&m_user, g_m_user);
    cudaGetSymbolAddress((void**)&m_item, g_m_item);
    cudaGetSymbolAddress((void**)&cnt_u, g_cnt_user);
    cudaGetSymbolAddress((void**)&cnt_i, g_cnt_item);
    cudaGetSymbolAddress((void**)&ind_u, g_ind_user);
    cudaGetSymbolAddress((void**)&ind_i, g_ind_item);
    cudaGetSymbolAddress((void**)&cur_u, g_cur_user);
    cudaGetSymbolAddress((void**)&cur_i, g_cur_item);
    cudaGetSymbolAddress((void**)&csr_u, g_csr_user);
    cudaGetSymbolAddress((void**)&csr_i, g_csr_item);
    cudaGetSymbolAddress((void**)&bs_u, g_bs_user);
    cudaGetSymbolAddress((void**)&bs_i, g_bs_item);

    const int EB = (NEDGE + 255) / 256;
    const int IB_U = (NUSER + 1023) / 1024;
    const int IB_I = (NITEM + 1023) / 1024;

    k_zero2<<<512, 256>>>(cnt_i, NITEM, cnt_u, NUSER);
    k_hist<<<EB, 256>>>(dst_ui, NEDGE, cnt_i);
    k_hist<<<EB, 256>>>(dst_iu, NEDGE, cnt_u);
    k_scan_block<<<IB_I, 1024>>>(cnt_i, NITEM, ind_i, bs_i);
    k_scan_block<<<IB_U, 1024>>>(cnt_u, NUSER, ind_u, bs_u);
    k_scan_bsums<<<1, 1024>>>(bs_i, IB_I);
    k_scan_bsums<<<1, 1024>>>(bs_u, IB_U);
    k_scan_final<<<(NITEM + 255) / 256, 256>>>(cnt_i, NITEM, ind_i, bs_i, cur_i);
    k_scan_final<<<(NUSER + 255) / 256, 256>>>(cnt_u, NUSER, ind_u, bs_u, cur_u);
    k_scatter<<<EB, 256>>>(src_ui, dst_ui, NEDGE, cur_i, csr_i);
    k_scatter<<<EB, 256>>>(src_iu, dst_iu, NEDGE, cur_u, csr_u);

    k_temporal_mma<<<148, TPB, TEMP_SMEM>>>(x_user, seed, t_user, b_user, teWu, tebu, xu, NUSER);
    k_temporal_mma<<<148, TPB, TEMP_SMEM>>>(x_item, seed, t_item, b_item, teWi, tebi, xi, NITEM);

    for (int l = 0; l < 2; l++) {
        size_t wo = (size_t)l * C * C;
        size_t vo = (size_t)l * C;
        k_agg<<<(NITEM * 32 + 255) / 256, 256>>>(xu, ind_i, csr_i, m_item, NITEM);
        k_agg<<<(NUSER * 32 + 255) / 256, 256>>>(xi, ind_u, csr_u, m_user, NUSER);
        k_sage_mma<<<148, TPB, SAGE_SMEM>>>(m_item, xi, Wl_ui + wo, bl_ui + vo, Wr_ui + wo,
                                            g_i + vo, be_i + vo, NITEM);
        k_sage_mma<<<148, TPB, SAGE_SMEM>>>(m_user, xu, Wl_iu + wo, bl_iu + vo, Wr_iu + wo,
                                            g_u + vo, be_u + vo, NUSER);
    }
}